// round 1
// baseline (speedup 1.0000x reference)
#include <cuda_runtime.h>
#include <cuda_bf16.h>

// ---------------------------------------------------------------------------
// CharEmbeddingCNN: embed + 3x conv1d(k=3,4,5) + maxpool + relu + len-mask.
//
// Strategy: conv over embedded chars == per-tap char->vector lookup tables.
//   C_kj[c, o] = sum_i W_k[o, i, j] * emb[c, i]      (12 tables, 256x256 each)
//   y_k[n,o,t] = b_k[o] + sum_j C_kj[x[n,t+j], o]
//   out[n,o]   = mask(n) * relu(max_{k,t} y_k[n,o,t])
//
// Stage 1: build the 12 tables (12 GEMMs 256x256x256) into g_tbl (3 MB).
// Stage 2: SMEM-staged lookup/accumulate/max kernel.
// ---------------------------------------------------------------------------

#define EMB   256
#define LSEQ  20
#define NTOT  8192            // 64 * 128
#define NPC   222             // n per CTA (37 groups * 222 >= 8192)
#define NGRP  37
#define OTILES 8              // 8 tiles of 32 outputs
#define TBL_BYTES 32768       // per-table SMEM slice: 256 chars * 32 floats * 4B
#define SMEM_CHARS_OFF (5 * TBL_BYTES)
#define SMEM_TOTAL (SMEM_CHARS_OFF + NPC * LSEQ * 2)

__device__ __align__(16) float g_tbl[12 * 256 * 256];

// ---------------------------------------------------------------------------
// Stage 1: build lookup tables. Table t in [0,12):
//   t 0..2  -> k=3, j=t
//   t 3..6  -> k=4, j=t-3
//   t 7..11 -> k=5, j=t-7
// g_tbl[t*65536 + c*256 + o] = sum_i emb[c*256+i] * w_k[o*256*k + i*k + j]
// ---------------------------------------------------------------------------
__global__ void build_tables(const float* __restrict__ emb,
                             const float* __restrict__ w3,
                             const float* __restrict__ w4,
                             const float* __restrict__ w5)
{
    const int tbl = blockIdx.x;
    const int c0  = blockIdx.y * 64;
    const int o0  = blockIdx.z * 64;

    int k, j; const float* w;
    if (tbl < 3)      { k = 3; j = tbl;     w = w3; }
    else if (tbl < 7) { k = 4; j = tbl - 3; w = w4; }
    else              { k = 5; j = tbl - 7; w = w5; }
    const int wk = 256 * k;

    __shared__ float As[16][65];   // [ki][ci], padded
    __shared__ float Bs[16][68];   // [ki][oi], padded (row 272B: 16B aligned)

    const int tid = threadIdx.x;           // 256 threads
    const int tx = tid & 15, ty = tid >> 4;

    float acc[4][4];
    #pragma unroll
    for (int i = 0; i < 4; i++)
        #pragma unroll
        for (int u = 0; u < 4; u++) acc[i][u] = 0.0f;

    for (int kk = 0; kk < 256; kk += 16) {
        #pragma unroll
        for (int r = 0; r < 4; r++) {
            int idx = tid + r * 256;
            int ci = idx >> 4, ki = idx & 15;
            As[ki][ci] = emb[(c0 + ci) * 256 + kk + ki];
        }
        #pragma unroll
        for (int r = 0; r < 4; r++) {
            int idx = tid + r * 256;
            int oi = idx >> 4, ki = idx & 15;
            Bs[ki][oi] = w[(o0 + oi) * wk + (kk + ki) * k + j];
        }
        __syncthreads();
        #pragma unroll
        for (int ki = 0; ki < 16; ki++) {
            float a[4], b[4];
            #pragma unroll
            for (int u = 0; u < 4; u++) a[u] = As[ki][ty * 4 + u];
            #pragma unroll
            for (int u = 0; u < 4; u++) b[u] = Bs[ki][tx * 4 + u];
            #pragma unroll
            for (int i = 0; i < 4; i++)
                #pragma unroll
                for (int u = 0; u < 4; u++)
                    acc[i][u] += a[i] * b[u];
        }
        __syncthreads();
    }

    #pragma unroll
    for (int i = 0; i < 4; i++) {
        int c = c0 + ty * 4 + i;
        float4 v = make_float4(acc[i][0], acc[i][1], acc[i][2], acc[i][3]);
        *reinterpret_cast<float4*>(&g_tbl[tbl * 65536 + c * 256 + o0 + tx * 4]) = v;
    }
}

// ---------------------------------------------------------------------------
// Stage 2: lookup + accumulate + max-pool + relu + mask.
// One phase per kernel size k; table slices staged in SMEM; result folded
// into out[] via max (out pre-zeroed; relu commutes with max).
// ---------------------------------------------------------------------------
template<int K>
__device__ __forceinline__ void run_phase(
    char* sm, const unsigned short* schars,
    const float* __restrict__ gphase,   // g_tbl + table_base * 65536
    const float* __restrict__ bias,
    const int* __restrict__ lens,
    float* __restrict__ out,
    int otile, int n_start, int n_count,
    int tid, int warp, int n_sub, int o4)
{
    __syncthreads();  // previous phase (or char staging) complete

    // Cooperative load of K table slices: K*256 rows of 32 floats (o-tile).
    const int total4 = K * 2048;
    for (int idx = tid; idx < total4; idx += 512) {
        int j   = idx >> 11;
        int rem = idx & 2047;
        int c   = rem >> 3;
        int f   = rem & 7;
        float4 v = *reinterpret_cast<const float4*>(
            gphase + j * 65536 + c * 256 + otile * 32 + f * 4);
        *reinterpret_cast<float4*>(sm + (j * 256 + c) * 128 + f * 16) = v;
    }
    __syncthreads();

    const float4 bv = *reinterpret_cast<const float4*>(bias + otile * 32 + o4 * 4);
    const unsigned lane_off = (unsigned)(o4 * 16);
    const int qtotal = (n_count + 3) >> 2;

    for (int q = warp; q < qtotal; q += 16) {
        const int nl  = q * 4 + n_sub;
        const int nlc = (nl < n_count) ? nl : (n_count - 1);

        unsigned a[LSEQ];
        #pragma unroll
        for (int p = 0; p < LSEQ; p++)
            a[p] = (unsigned)schars[nlc * LSEQ + p] + lane_off;

        float mx = -3.402823466e38f, my = mx, mz = mx, mw = mx;
        #pragma unroll
        for (int t = 0; t <= LSEQ - K; t++) {
            float4 s = *reinterpret_cast<const float4*>(sm + a[t]);
            #pragma unroll
            for (int j = 1; j < K; j++) {
                float4 r = *reinterpret_cast<const float4*>(
                    sm + (unsigned)(j * TBL_BYTES) + a[t + j]);
                s.x += r.x; s.y += r.y; s.z += r.z; s.w += r.w;
            }
            mx = fmaxf(mx, s.x); my = fmaxf(my, s.y);
            mz = fmaxf(mz, s.z); mw = fmaxf(mw, s.w);
        }

        if (nl < n_count) {
            const int n = n_start + nl;
            if (lens[n] != 0) {
                float4 r;
                r.x = fmaxf(mx + bv.x, 0.0f);
                r.y = fmaxf(my + bv.y, 0.0f);
                r.z = fmaxf(mz + bv.z, 0.0f);
                r.w = fmaxf(mw + bv.w, 0.0f);
                float4* po = reinterpret_cast<float4*>(
                    &out[(size_t)n * 256 + otile * 32 + o4 * 4]);
                float4 cur = *po;
                cur.x = fmaxf(cur.x, r.x);
                cur.y = fmaxf(cur.y, r.y);
                cur.z = fmaxf(cur.z, r.z);
                cur.w = fmaxf(cur.w, r.w);
                *po = cur;
            }
        }
    }
}

__global__ void __launch_bounds__(512, 1)
cnn_pool_kernel(const int* __restrict__ x, const int* __restrict__ lens,
                const float* __restrict__ b3, const float* __restrict__ b4,
                const float* __restrict__ b5, float* __restrict__ out)
{
    extern __shared__ char sm[];
    const int group = blockIdx.x;
    const int otile = blockIdx.y;
    const int n_start = group * NPC;
    const int n_count = min(NTOT - n_start, NPC);

    unsigned short* schars = reinterpret_cast<unsigned short*>(sm + SMEM_CHARS_OFF);
    const int tid = threadIdx.x;

    // Stage char offsets (c * 128 bytes, the table row stride) once per CTA.
    for (int i = tid; i < n_count * LSEQ; i += 512)
        schars[i] = (unsigned short)(x[n_start * LSEQ + i] << 7);

    const int lane  = tid & 31;
    const int warp  = tid >> 5;
    const int n_sub = lane >> 3;
    const int o4    = lane & 7;

    run_phase<3>(sm, schars, g_tbl,             b3, lens, out, otile, n_start, n_count, tid, warp, n_sub, o4);
    run_phase<4>(sm, schars, g_tbl + 3 * 65536, b4, lens, out, otile, n_start, n_count, tid, warp, n_sub, o4);
    run_phase<5>(sm, schars, g_tbl + 7 * 65536, b5, lens, out, otile, n_start, n_count, tid, warp, n_sub, o4);
}

// ---------------------------------------------------------------------------
extern "C" void kernel_launch(void* const* d_in, const int* in_sizes, int n_in,
                              void* d_out, int out_size)
{
    const int*   x    = (const int*)  d_in[0];
    const int*   lens = (const int*)  d_in[1];
    const float* emb  = (const float*)d_in[2];
    const float* w3   = (const float*)d_in[3];
    const float* b3   = (const float*)d_in[4];
    const float* w4   = (const float*)d_in[5];
    const float* b4   = (const float*)d_in[6];
    const float* w5   = (const float*)d_in[7];
    const float* b5   = (const float*)d_in[8];
    float* out = (float*)d_out;

    // Output must be zero for masked rows; phases fold in via max().
    cudaMemsetAsync(d_out, 0, (size_t)out_size * sizeof(float), 0);

    build_tables<<<dim3(12, 4, 4), 256>>>(emb, w3, w4, w5);

    cudaFuncSetAttribute(cnn_pool_kernel,
                         cudaFuncAttributeMaxDynamicSharedMemorySize, SMEM_TOTAL);
    cnn_pool_kernel<<<dim3(NGRP, OTILES), 512, SMEM_TOTAL>>>(x, lens, b3, b4, b5, out);
}

// round 2
// speedup vs baseline: 1.8051x; 1.8051x over previous
#include <cuda_runtime.h>
#include <cuda_fp16.h>

// ---------------------------------------------------------------------------
// CharEmbeddingCNN: embed + 3x conv1d(k=3,4,5) + maxpool + relu + len-mask.
//
//   C_kj[c, o] = sum_i W_k[o, i, j] * emb[c, i]      (12 tables, 256x256, fp16)
//   y_k[n,o,t] = b_k[o] + sum_j C_kj[x[n,t+j], o]
//   out[n,o]   = mask(n) * relu(max_{k,t} y_k[n,o,t])
//
// fp16 tables let one 128-byte SMEM row carry 64 outputs -> half the crossbar
// traffic and half the per-output instruction count vs fp32, with the same
// conflict-free access pattern (4 n x 8 lanes x 16B per warp).
// ---------------------------------------------------------------------------

#define EMB   256
#define LSEQ  20
#define NTOT  8192            // 64 * 128
#define NPC   111             // n per CTA (74 groups * 111 >= 8192)
#define NGRP  74
#define OTILES 4              // 4 tiles of 64 outputs
#define TBL_BYTES 32768       // per-table SMEM slice: 256 chars * 64 halves * 2B
#define SMEM_CHARS_OFF (5 * TBL_BYTES)
#define SMEM_TOTAL (SMEM_CHARS_OFF + NPC * LSEQ * 2)

__device__ __align__(16) __half g_tbl_h[12 * 256 * 256];

// ---------------------------------------------------------------------------
// Stage 1: build lookup tables (fp32 accumulate, fp16 store).
//   t 0..2 -> k=3, j=t ; t 3..6 -> k=4, j=t-3 ; t 7..11 -> k=5, j=t-7
// ---------------------------------------------------------------------------
__global__ void build_tables(const float* __restrict__ emb,
                             const float* __restrict__ w3,
                             const float* __restrict__ w4,
                             const float* __restrict__ w5)
{
    const int tbl = blockIdx.x;
    const int c0  = blockIdx.y * 64;
    const int o0  = blockIdx.z * 64;

    int k, j; const float* w;
    if (tbl < 3)      { k = 3; j = tbl;     w = w3; }
    else if (tbl < 7) { k = 4; j = tbl - 3; w = w4; }
    else              { k = 5; j = tbl - 7; w = w5; }
    const int wk = 256 * k;

    __shared__ float As[16][65];
    __shared__ float Bs[16][68];

    const int tid = threadIdx.x;           // 256 threads
    const int tx = tid & 15, ty = tid >> 4;

    float acc[4][4];
    #pragma unroll
    for (int i = 0; i < 4; i++)
        #pragma unroll
        for (int u = 0; u < 4; u++) acc[i][u] = 0.0f;

    for (int kk = 0; kk < 256; kk += 16) {
        #pragma unroll
        for (int r = 0; r < 4; r++) {
            int idx = tid + r * 256;
            int ci = idx >> 4, ki = idx & 15;
            As[ki][ci] = emb[(c0 + ci) * 256 + kk + ki];
        }
        #pragma unroll
        for (int r = 0; r < 4; r++) {
            int idx = tid + r * 256;
            int oi = idx >> 4, ki = idx & 15;
            Bs[ki][oi] = w[(o0 + oi) * wk + (kk + ki) * k + j];
        }
        __syncthreads();
        #pragma unroll
        for (int ki = 0; ki < 16; ki++) {
            float a[4], b[4];
            #pragma unroll
            for (int u = 0; u < 4; u++) a[u] = As[ki][ty * 4 + u];
            #pragma unroll
            for (int u = 0; u < 4; u++) b[u] = Bs[ki][tx * 4 + u];
            #pragma unroll
            for (int i = 0; i < 4; i++)
                #pragma unroll
                for (int u = 0; u < 4; u++)
                    acc[i][u] += a[i] * b[u];
        }
        __syncthreads();
    }

    #pragma unroll
    for (int i = 0; i < 4; i++) {
        int c = c0 + ty * 4 + i;
        __half2 h01 = __floats2half2_rn(acc[i][0], acc[i][1]);
        __half2 h23 = __floats2half2_rn(acc[i][2], acc[i][3]);
        uint2 v;
        v.x = *reinterpret_cast<unsigned*>(&h01);
        v.y = *reinterpret_cast<unsigned*>(&h23);
        *reinterpret_cast<uint2*>(&g_tbl_h[tbl * 65536 + c * 256 + o0 + tx * 4]) = v;
    }
}

// ---------------------------------------------------------------------------
// Stage 2: lookup + accumulate (HADD2) + max (HMAX2) + bias/relu/mask (fp32).
// ---------------------------------------------------------------------------
template<int K>
__device__ __forceinline__ void run_phase(
    char* sm, const unsigned short* schars,
    const __half* __restrict__ gphase,
    const float* __restrict__ bias,
    const int* __restrict__ lens,
    float* __restrict__ out,
    int otile, int n_start, int n_count,
    int tid, int warp, int n_sub, int o8)
{
    __syncthreads();  // previous phase done reading SMEM

    // Stage K table slices: K*256 rows of 64 halves (128B rows).
    const int total16 = K * 2048;          // 16B chunks
    for (int idx = tid; idx < total16; idx += 512) {
        int j   = idx >> 11;
        int rem = idx & 2047;
        int c   = rem >> 3;
        int f   = rem & 7;
        uint4 v = *reinterpret_cast<const uint4*>(
            gphase + j * 65536 + c * 256 + otile * 64 + f * 8);
        *reinterpret_cast<uint4*>(sm + (j * 256 + c) * 128 + f * 16) = v;
    }
    __syncthreads();

    // Per-lane bias (8 outputs) in fp32.
    const float* bp = bias + otile * 64 + o8 * 8;
    float bb[8];
    #pragma unroll
    for (int i = 0; i < 8; i++) bb[i] = bp[i];

    const unsigned lane_off = (unsigned)(o8 * 16);
    const int qtotal = (n_count + 3) >> 2;
    const __half2 NEGINF = __float2half2_rn(-60000.0f);

    for (int q = warp; q < qtotal; q += 16) {
        const int nl  = q * 4 + n_sub;
        const int nlc = (nl < n_count) ? nl : (n_count - 1);

        unsigned a[LSEQ];
        #pragma unroll
        for (int p = 0; p < LSEQ; p++)
            a[p] = (unsigned)schars[nlc * LSEQ + p] + lane_off;

        __half2 m0 = NEGINF, m1 = NEGINF, m2 = NEGINF, m3 = NEGINF;
        #pragma unroll
        for (int t = 0; t <= LSEQ - K; t++) {
            uint4 su = *reinterpret_cast<const uint4*>(sm + a[t]);
            __half2 s0 = *reinterpret_cast<__half2*>(&su.x);
            __half2 s1 = *reinterpret_cast<__half2*>(&su.y);
            __half2 s2 = *reinterpret_cast<__half2*>(&su.z);
            __half2 s3 = *reinterpret_cast<__half2*>(&su.w);
            #pragma unroll
            for (int j = 1; j < K; j++) {
                uint4 ru = *reinterpret_cast<const uint4*>(
                    sm + (unsigned)(j * TBL_BYTES) + a[t + j]);
                s0 = __hadd2(s0, *reinterpret_cast<__half2*>(&ru.x));
                s1 = __hadd2(s1, *reinterpret_cast<__half2*>(&ru.y));
                s2 = __hadd2(s2, *reinterpret_cast<__half2*>(&ru.z));
                s3 = __hadd2(s3, *reinterpret_cast<__half2*>(&ru.w));
            }
            m0 = __hmax2(m0, s0);
            m1 = __hmax2(m1, s1);
            m2 = __hmax2(m2, s2);
            m3 = __hmax2(m3, s3);
        }

        if (nl < n_count) {
            const int n = n_start + nl;
            if (lens[n] != 0) {
                float2 f0 = __half22float2(m0);
                float2 f1 = __half22float2(m1);
                float2 f2 = __half22float2(m2);
                float2 f3 = __half22float2(m3);
                float r[8];
                r[0] = fmaxf(f0.x + bb[0], 0.0f);
                r[1] = fmaxf(f0.y + bb[1], 0.0f);
                r[2] = fmaxf(f1.x + bb[2], 0.0f);
                r[3] = fmaxf(f1.y + bb[3], 0.0f);
                r[4] = fmaxf(f2.x + bb[4], 0.0f);
                r[5] = fmaxf(f2.y + bb[5], 0.0f);
                r[6] = fmaxf(f3.x + bb[6], 0.0f);
                r[7] = fmaxf(f3.y + bb[7], 0.0f);
                float4* po = reinterpret_cast<float4*>(
                    &out[(size_t)n * 256 + otile * 64 + o8 * 8]);
                float4 c0v = po[0], c1v = po[1];
                c0v.x = fmaxf(c0v.x, r[0]); c0v.y = fmaxf(c0v.y, r[1]);
                c0v.z = fmaxf(c0v.z, r[2]); c0v.w = fmaxf(c0v.w, r[3]);
                c1v.x = fmaxf(c1v.x, r[4]); c1v.y = fmaxf(c1v.y, r[5]);
                c1v.z = fmaxf(c1v.z, r[6]); c1v.w = fmaxf(c1v.w, r[7]);
                po[0] = c0v; po[1] = c1v;
            }
        }
    }
}

__global__ void __launch_bounds__(512, 1)
cnn_pool_kernel(const int* __restrict__ x, const int* __restrict__ lens,
                const float* __restrict__ b3, const float* __restrict__ b4,
                const float* __restrict__ b5, float* __restrict__ out)
{
    extern __shared__ char sm[];
    const int group = blockIdx.x;
    const int otile = blockIdx.y;
    const int n_start = group * NPC;
    const int n_count = min(NTOT - n_start, NPC);

    unsigned short* schars = reinterpret_cast<unsigned short*>(sm + SMEM_CHARS_OFF);
    const int tid = threadIdx.x;

    // Stage char row offsets (char * 128B row stride) once per CTA.
    for (int i = tid; i < n_count * LSEQ; i += 512)
        schars[i] = (unsigned short)(x[n_start * LSEQ + i] << 7);

    const int lane  = tid & 31;
    const int warp  = tid >> 5;
    const int n_sub = lane >> 3;
    const int o8    = lane & 7;

    run_phase<3>(sm, schars, g_tbl_h,             b3, lens, out, otile, n_start, n_count, tid, warp, n_sub, o8);
    run_phase<4>(sm, schars, g_tbl_h + 3 * 65536, b4, lens, out, otile, n_start, n_count, tid, warp, n_sub, o8);
    run_phase<5>(sm, schars, g_tbl_h + 7 * 65536, b5, lens, out, otile, n_start, n_count, tid, warp, n_sub, o8);
}

// ---------------------------------------------------------------------------
extern "C" void kernel_launch(void* const* d_in, const int* in_sizes, int n_in,
                              void* d_out, int out_size)
{
    const int*   x    = (const int*)  d_in[0];
    const int*   lens = (const int*)  d_in[1];
    const float* emb  = (const float*)d_in[2];
    const float* w3   = (const float*)d_in[3];
    const float* b3   = (const float*)d_in[4];
    const float* w4   = (const float*)d_in[5];
    const float* b4   = (const float*)d_in[6];
    const float* w5   = (const float*)d_in[7];
    const float* b5   = (const float*)d_in[8];
    float* out = (float*)d_out;

    // Output must be zero for masked rows; phases fold in via max().
    cudaMemsetAsync(d_out, 0, (size_t)out_size * sizeof(float), 0);

    build_tables<<<dim3(12, 4, 4), 256>>>(emb, w3, w4, w5);

    cudaFuncSetAttribute(cnn_pool_kernel,
                         cudaFuncAttributeMaxDynamicSharedMemorySize, SMEM_TOTAL);
    cnn_pool_kernel<<<dim3(NGRP, OTILES), 512, SMEM_TOTAL>>>(x, lens, b3, b4, b5, out);
}

// round 3
// speedup vs baseline: 2.4065x; 1.3332x over previous
#include <cuda_runtime.h>
#include <cuda_fp16.h>

// ---------------------------------------------------------------------------
// CharEmbeddingCNN: embed + 3x conv1d(k=3,4,5) + maxpool + relu + len-mask.
//
//   C_kj[c, o] = sum_i W_k[o, i, j] * emb[c, i]      (12 tables, 256x256, fp16)
//   y_k[n,o,t] = b_k[o] + sum_j C_kj[x[n,t+j], o]
//   out[n,o]   = mask(n) * relu(max_{k,t} y_k[n,o,t])
//
// R3: 1024-thread CTAs (32 warps/SM, 64-reg cap), single-wave grid (148 CTAs),
// cross-phase max carried in registers (single pure store, no memset, free
// relu), packed char-offset loads.
// ---------------------------------------------------------------------------

#define EMB   256
#define LSEQ  20
#define NTOT  8192            // 64 * 128
#define NPC   222             // n per CTA (37 groups)
#define NGRP  37
#define OTILES 4              // 4 tiles of 64 outputs
#define TBL_BYTES 32768       // per-table SMEM slice: 256 chars * 64 halves * 2B
#define CHSTRIDE 24           // shorts per n (20 used, 48B padded for uint4)
#define SMEM_CHARS_OFF (5 * TBL_BYTES)
#define SMEM_TOTAL (SMEM_CHARS_OFF + NPC * CHSTRIDE * 2)

__device__ __align__(16) __half g_tbl_h[12 * 256 * 256];

// ---------------------------------------------------------------------------
// Stage 1: build lookup tables (fp32 accumulate, fp16 store).
//   t 0..2 -> k=3, j=t ; t 3..6 -> k=4, j=t-3 ; t 7..11 -> k=5, j=t-7
// ---------------------------------------------------------------------------
__global__ void build_tables(const float* __restrict__ emb,
                             const float* __restrict__ w3,
                             const float* __restrict__ w4,
                             const float* __restrict__ w5)
{
    const int tbl = blockIdx.x;
    const int c0  = blockIdx.y * 64;
    const int o0  = blockIdx.z * 64;

    int k, j; const float* w;
    if (tbl < 3)      { k = 3; j = tbl;     w = w3; }
    else if (tbl < 7) { k = 4; j = tbl - 3; w = w4; }
    else              { k = 5; j = tbl - 7; w = w5; }
    const int wk = 256 * k;

    __shared__ float As[16][65];
    __shared__ float Bs[16][68];

    const int tid = threadIdx.x;           // 256 threads
    const int tx = tid & 15, ty = tid >> 4;

    float acc[4][4];
    #pragma unroll
    for (int i = 0; i < 4; i++)
        #pragma unroll
        for (int u = 0; u < 4; u++) acc[i][u] = 0.0f;

    for (int kk = 0; kk < 256; kk += 16) {
        #pragma unroll
        for (int r = 0; r < 4; r++) {
            int idx = tid + r * 256;
            int ci = idx >> 4, ki = idx & 15;
            As[ki][ci] = emb[(c0 + ci) * 256 + kk + ki];
        }
        #pragma unroll
        for (int r = 0; r < 4; r++) {
            int idx = tid + r * 256;
            int oi = idx >> 4, ki = idx & 15;
            Bs[ki][oi] = w[(o0 + oi) * wk + (kk + ki) * k + j];
        }
        __syncthreads();
        #pragma unroll
        for (int ki = 0; ki < 16; ki++) {
            float a[4], b[4];
            #pragma unroll
            for (int u = 0; u < 4; u++) a[u] = As[ki][ty * 4 + u];
            #pragma unroll
            for (int u = 0; u < 4; u++) b[u] = Bs[ki][tx * 4 + u];
            #pragma unroll
            for (int i = 0; i < 4; i++)
                #pragma unroll
                for (int u = 0; u < 4; u++)
                    acc[i][u] += a[i] * b[u];
        }
        __syncthreads();
    }

    #pragma unroll
    for (int i = 0; i < 4; i++) {
        int c = c0 + ty * 4 + i;
        __half2 h01 = __floats2half2_rn(acc[i][0], acc[i][1]);
        __half2 h23 = __floats2half2_rn(acc[i][2], acc[i][3]);
        uint2 v;
        v.x = *reinterpret_cast<unsigned*>(&h01);
        v.y = *reinterpret_cast<unsigned*>(&h23);
        *reinterpret_cast<uint2*>(&g_tbl_h[tbl * 65536 + c * 256 + o0 + tx * 4]) = v;
    }
}

// ---------------------------------------------------------------------------
// Stage 2 phase: stage K table slices, lookup+HADD2+HMAX2, fold (max + bias)
// into the cross-phase accumulator.
// ---------------------------------------------------------------------------
template<int K>
__device__ __forceinline__ void run_phase(
    char* sm, const unsigned short* schars,
    const __half* __restrict__ gphase,
    const float* __restrict__ bias,
    __half2 acc[2][4],
    int otile, int n_count, int qtotal,
    int tid, int warp, int n_sub, unsigned lane_off)
{
    __syncthreads();  // previous phase done reading SMEM

    // Stage K table slices: K*256 rows of 64 halves (128B rows).
    const int total16 = K * 2048;          // 16B chunks
    for (int idx = tid; idx < total16; idx += 1024) {
        int j   = idx >> 11;
        int rem = idx & 2047;
        int c   = rem >> 3;
        int f   = rem & 7;
        uint4 v = *reinterpret_cast<const uint4*>(
            gphase + j * 65536 + c * 256 + otile * 64 + f * 8);
        *reinterpret_cast<uint4*>(sm + (j * 256 + c) * 128 + f * 16) = v;
    }
    __syncthreads();

    // Per-lane bias (8 outputs) as half2.
    const float* bp = bias + otile * 64 + (lane_off >> 1);
    __half2 bh[4];
    #pragma unroll
    for (int c = 0; c < 4; c++)
        bh[c] = __floats2half2_rn(bp[2 * c], bp[2 * c + 1]);

    const __half2 NEGINF = __float2half2_rn(-60000.0f);

    #pragma unroll
    for (int it = 0; it < 2; it++) {
        const int q = warp + it * 32;
        if (q < qtotal) {
            const int nl  = q * 4 + n_sub;
            const int nlc = (nl < n_count) ? nl : (n_count - 1);

            // Packed char-row-offset loads: 20 shorts in 3 vector LDS.
            const unsigned short* cp = schars + nlc * CHSTRIDE;
            uint4 p0 = *reinterpret_cast<const uint4*>(cp);
            uint4 p1 = *reinterpret_cast<const uint4*>(cp + 8);
            uint2 p2 = *reinterpret_cast<const uint2*>(cp + 16);
            unsigned pk[10] = {p0.x, p0.y, p0.z, p0.w,
                               p1.x, p1.y, p1.z, p1.w, p2.x, p2.y};
            unsigned a[LSEQ];
            #pragma unroll
            for (int p = 0; p < LSEQ; p++)
                a[p] = ((pk[p >> 1] >> (16 * (p & 1))) & 0xFFFFu) + lane_off;

            __half2 m0 = NEGINF, m1 = NEGINF, m2 = NEGINF, m3 = NEGINF;
            #pragma unroll
            for (int t = 0; t <= LSEQ - K; t++) {
                uint4 su = *reinterpret_cast<const uint4*>(sm + a[t]);
                __half2 s0 = *reinterpret_cast<__half2*>(&su.x);
                __half2 s1 = *reinterpret_cast<__half2*>(&su.y);
                __half2 s2 = *reinterpret_cast<__half2*>(&su.z);
                __half2 s3 = *reinterpret_cast<__half2*>(&su.w);
                #pragma unroll
                for (int j = 1; j < K; j++) {
                    uint4 ru = *reinterpret_cast<const uint4*>(
                        sm + (unsigned)(j * TBL_BYTES) + a[t + j]);
                    s0 = __hadd2(s0, *reinterpret_cast<__half2*>(&ru.x));
                    s1 = __hadd2(s1, *reinterpret_cast<__half2*>(&ru.y));
                    s2 = __hadd2(s2, *reinterpret_cast<__half2*>(&ru.z));
                    s3 = __hadd2(s3, *reinterpret_cast<__half2*>(&ru.w));
                }
                m0 = __hmax2(m0, s0);
                m1 = __hmax2(m1, s1);
                m2 = __hmax2(m2, s2);
                m3 = __hmax2(m3, s3);
            }

            // Fold (phase max + bias) into cross-phase accumulator (>=0 ->
            // relu is implicit in the init-at-zero accumulator).
            acc[it][0] = __hmax2(acc[it][0], __hadd2(m0, bh[0]));
            acc[it][1] = __hmax2(acc[it][1], __hadd2(m1, bh[1]));
            acc[it][2] = __hmax2(acc[it][2], __hadd2(m2, bh[2]));
            acc[it][3] = __hmax2(acc[it][3], __hadd2(m3, bh[3]));
        }
    }
}

__global__ void __launch_bounds__(1024, 1)
cnn_pool_kernel(const int* __restrict__ x, const int* __restrict__ lens,
                const float* __restrict__ b3, const float* __restrict__ b4,
                const float* __restrict__ b5, float* __restrict__ out)
{
    extern __shared__ char sm[];
    const int group   = blockIdx.x;
    const int otile   = blockIdx.y;
    const int n_start = group * NPC;
    const int n_count = min(NTOT - n_start, NPC);

    unsigned short* schars = reinterpret_cast<unsigned short*>(sm + SMEM_CHARS_OFF);
    const int tid = threadIdx.x;

    // Stage char row offsets (char * 128B row stride), padded stride 24.
    for (int i = tid; i < n_count * LSEQ; i += 1024) {
        int n = i / LSEQ, p = i - n * LSEQ;
        schars[n * CHSTRIDE + p] =
            (unsigned short)(x[(n_start + n) * LSEQ + p] << 7);
    }

    const int lane  = tid & 31;
    const int warp  = tid >> 5;
    const int n_sub = lane >> 3;
    const unsigned lane_off = (unsigned)((lane & 7) * 16);
    const int qtotal = (n_count + 3) >> 2;

    __half2 acc[2][4];
    #pragma unroll
    for (int i = 0; i < 2; i++)
        #pragma unroll
        for (int c = 0; c < 4; c++) acc[i][c] = __float2half2_rn(0.0f);

    run_phase<3>(sm, schars, g_tbl_h,             b3, acc, otile, n_count, qtotal, tid, warp, n_sub, lane_off);
    run_phase<4>(sm, schars, g_tbl_h + 3 * 65536, b4, acc, otile, n_count, qtotal, tid, warp, n_sub, lane_off);
    run_phase<5>(sm, schars, g_tbl_h + 7 * 65536, b5, acc, otile, n_count, qtotal, tid, warp, n_sub, lane_off);

    // Epilogue: one pure store per (n, 8-output slice). Masked rows -> zeros.
    #pragma unroll
    for (int it = 0; it < 2; it++) {
        const int q  = warp + it * 32;
        const int nl = q * 4 + n_sub;
        if (q < qtotal && nl < n_count) {
            const int n = n_start + nl;
            float4 o0 = make_float4(0.f, 0.f, 0.f, 0.f);
            float4 o1 = o0;
            if (lens[n] != 0) {
                float2 f0 = __half22float2(acc[it][0]);
                float2 f1 = __half22float2(acc[it][1]);
                float2 f2 = __half22float2(acc[it][2]);
                float2 f3 = __half22float2(acc[it][3]);
                o0 = make_float4(f0.x, f0.y, f1.x, f1.y);
                o1 = make_float4(f2.x, f2.y, f3.x, f3.y);
            }
            float4* po = reinterpret_cast<float4*>(
                &out[(size_t)n * 256 + otile * 64 + (lane_off >> 1)]);
            po[0] = o0;
            po[1] = o1;
        }
    }
}

// ---------------------------------------------------------------------------
extern "C" void kernel_launch(void* const* d_in, const int* in_sizes, int n_in,
                              void* d_out, int out_size)
{
    const int*   x    = (const int*)  d_in[0];
    const int*   lens = (const int*)  d_in[1];
    const float* emb  = (const float*)d_in[2];
    const float* w3   = (const float*)d_in[3];
    const float* b3   = (const float*)d_in[4];
    const float* w4   = (const float*)d_in[5];
    const float* b4   = (const float*)d_in[6];
    const float* w5   = (const float*)d_in[7];
    const float* b5   = (const float*)d_in[8];
    float* out = (float*)d_out;

    build_tables<<<dim3(12, 4, 4), 256>>>(emb, w3, w4, w5);

    cudaFuncSetAttribute(cnn_pool_kernel,
                         cudaFuncAttributeMaxDynamicSharedMemorySize, SMEM_TOTAL);
    cnn_pool_kernel<<<dim3(NGRP, OTILES), 1024, SMEM_TOTAL>>>(x, lens, b3, b4, b5, out);
}